// round 15
// baseline (speedup 1.0000x reference)
#include <cuda_runtime.h>
#include <cstdint>

#define NBOX   8192
#define CLS    81
#define NPAD   300
#define NWORDS (NBOX / 32)      // 256 words per mask row
#define NCH2   (NBOX / 128)     // 64 scan chunks of 128 boxes
#define MAXK   8                // staged keep rows per chunk (overflow -> direct)

typedef unsigned long long u64;

// ------------------------- device scratch (static, no allocs) --------------
__device__ float4   g_selv[NBOX];     // decoded boxes (orig order)
__device__ u64      g_key[NBOX];      // composite sort keys
__device__ float4   g_sbox[NBOX];     // boxes in sorted order
__device__ float    g_sarea[NBOX];    // areas in sorted order
__device__ int      g_orig[NBOX];     // sorted pos -> original idx
__device__ unsigned g_masks[(size_t)NBOX * NWORDS]; // sorted-space IoU>0.5

// ------------------------- cp.async helpers --------------------------------
__device__ __forceinline__ void cp_async16(void* smem_dst, const void* gmem_src) {
    unsigned saddr = (unsigned)__cvta_generic_to_shared(smem_dst);
    asm volatile("cp.async.cg.shared.global [%0], [%1], 16;\n"
                 :: "r"(saddr), "l"(gmem_src));
}
__device__ __forceinline__ void cp_async4(void* smem_dst, const void* gmem_src) {
    unsigned saddr = (unsigned)__cvta_generic_to_shared(smem_dst);
    asm volatile("cp.async.ca.shared.global [%0], [%1], 4;\n"
                 :: "r"(saddr), "l"(gmem_src));
}
__device__ __forceinline__ void cp_commit() {
    asm volatile("cp.async.commit_group;\n" ::);
}
__device__ __forceinline__ void cp_wait1() {
    asm volatile("cp.async.wait_group 1;\n" ::: "memory");
}

// ---------------------------------------------------------------------------
// Kernel 1: per-row argmax / max + bbox decode + sort-key build. 1 warp/row.
// ---------------------------------------------------------------------------
__global__ void decode_kernel(const float* __restrict__ meta,
                              const float* __restrict__ deltas,
                              const float* __restrict__ proposals,
                              const float* __restrict__ scores) {
    int row  = (int)((blockIdx.x * blockDim.x + threadIdx.x) >> 5);
    int lane = threadIdx.x & 31;
    if (row >= NBOX) return;

    const float* srow = scores + (size_t)row * CLS;
    float best = -1.0f;
    int   bidx = 0x7FFFFFFF;
    float ms   = -1.0f;
    for (int j = lane; j < CLS; j += 32) {
        float v = srow[j];
        if (v > best) { best = v; bidx = j; }
        if (j >= 1) ms = fmaxf(ms, v);
    }
    #pragma unroll
    for (int off = 16; off; off >>= 1) {
        float ov = __shfl_down_sync(0xffffffffu, best, off);
        int   oi = __shfl_down_sync(0xffffffffu, bidx, off);
        float om = __shfl_down_sync(0xffffffffu, ms,   off);
        if (ov > best || (ov == best && oi < bidx)) { best = ov; bidx = oi; }
        ms = fmaxf(ms, om);
    }

    if (lane == 0) {
        float scale = meta[2];
        const float* p = proposals + (size_t)row * 4;
        float x1 = p[0] / scale, y1 = p[1] / scale;
        float x2 = p[2] / scale, y2 = p[3] / scale;
        float w  = x2 - x1 + 1.0f, h = y2 - y1 + 1.0f;
        float cx = x1 + 0.5f * w,  cy = y1 + 0.5f * h;

        const float* d = deltas + (size_t)row * (4 * CLS) + 4 * bidx;
        float pcx = d[0] * w + cx;
        float pcy = d[1] * h + cy;
        float pw  = expf(d[2]) * w;
        float ph  = expf(d[3]) * h;

        float W1 = meta[1] - 1.0f;
        float H1 = meta[0] - 1.0f;
        float ox1 = fminf(fmaxf(pcx - 0.5f * pw, 0.0f), W1);
        float oy1 = fminf(fmaxf(pcy - 0.5f * ph, 0.0f), H1);
        float ox2 = fminf(fmaxf(pcx + 0.5f * pw, 0.0f), W1);
        float oy2 = fminf(fmaxf(pcy + 0.5f * ph, 0.0f), H1);

        g_selv[row] = make_float4(ox1, oy1, ox2, oy2);
        unsigned int sb = __float_as_uint(ms);   // scores >= 0 -> monotonic bits
        g_key[row] = ((u64)sb << 13) | (u64)(8191 - row);   // all keys distinct
    }
}

// ---------------------------------------------------------------------------
// Kernel 2: rank-by-counting + scatter into sorted order. 256 blocks.
// ---------------------------------------------------------------------------
__global__ void __launch_bounds__(256)
rank_kernel() {
    extern __shared__ u64 keys[];   // 64 KB
    const int tid = threadIdx.x;
    for (int i = tid; i < NBOX; i += 256) keys[i] = g_key[i];
    __syncthreads();

    const int warp = tid >> 5, lane = tid & 31;
    const int row0 = blockIdx.x * 32 + warp * 4;

    u64 rk0 = keys[row0 + 0];
    u64 rk1 = keys[row0 + 1];
    u64 rk2 = keys[row0 + 2];
    u64 rk3 = keys[row0 + 3];
    int c0 = 0, c1 = 0, c2 = 0, c3 = 0;

    #pragma unroll 4
    for (int c = lane; c < NBOX; c += 32) {
        u64 kc = keys[c];
        c0 += (kc > rk0);
        c1 += (kc > rk1);
        c2 += (kc > rk2);
        c3 += (kc > rk3);
    }
    #pragma unroll
    for (int off = 16; off; off >>= 1) {
        c0 += __shfl_down_sync(0xffffffffu, c0, off);
        c1 += __shfl_down_sync(0xffffffffu, c1, off);
        c2 += __shfl_down_sync(0xffffffffu, c2, off);
        c3 += __shfl_down_sync(0xffffffffu, c3, off);
    }
    if (lane == 0) {
        int rr[4] = {c0, c1, c2, c3};
        #pragma unroll
        for (int q = 0; q < 4; q++) {
            int i = row0 + q, r = rr[q];
            float4 b = g_selv[i];
            g_sbox[r]  = b;
            g_sarea[r] = fmaxf(b.z - b.x, 0.0f) * fmaxf(b.w - b.y, 0.0f);
            g_orig[r]  = i;
        }
    }
}

// ---------------------------------------------------------------------------
// Kernel 3: sorted-space IoU>0.5 bitmask, upper-triangle tiles only (1152).
// ---------------------------------------------------------------------------
__constant__ int c_prefix[9] = {0, 256, 480, 672, 832, 960, 1056, 1120, 1152};

__global__ void __launch_bounds__(256)
mask_kernel() {
    __shared__ float4 rbs[32];
    __shared__ float  ras[32];
    __shared__ float4 cbT[32 * 33];
    __shared__ float  caT[32 * 33];

    const int t = blockIdx.x;
    int g = 0;
    #pragma unroll
    for (int h = 1; h < 8; h++) g += (t >= c_prefix[h]);
    const int tp   = t - c_prefix[g];
    const int span = 8 - g;
    const int r    = tp / span;
    const int rb   = g * 32 + r;
    const int cb   = g + (tp - r * span);

    const int rowbase = rb * 32;
    const int colbase = cb * 1024;
    const int tid = threadIdx.x;

    if (tid < 32) {
        rbs[tid] = g_sbox[rowbase + tid];
        ras[tid] = g_sarea[rowbase + tid];
    }
    for (int jj = tid; jj < 1024; jj += 256) {
        int w = jj >> 5, bb = jj & 31;
        cbT[bb * 33 + w] = g_sbox[colbase + jj];
        caT[bb * 33 + w] = g_sarea[colbase + jj];
    }
    __syncthreads();

    const int r0 = tid >> 5;
    const int w  = tid & 31;
    float4 bi[4];
    float  si[4];
    #pragma unroll
    for (int k = 0; k < 4; k++) {
        bi[k] = rbs[r0 + 8 * k];
        si[k] = ras[r0 + 8 * k] + 1e-8f;
    }
    unsigned bits0 = 0, bits1 = 0, bits2 = 0, bits3 = 0;

    #pragma unroll
    for (int b = 0; b < 32; b++) {
        float4 bj = cbT[b * 33 + w];
        float  aj = caT[b * 33 + w];
        #pragma unroll
        for (int k = 0; k < 4; k++) {
            float xx1 = fmaxf(bi[k].x, bj.x), yy1 = fmaxf(bi[k].y, bj.y);
            float xx2 = fminf(bi[k].z, bj.z), yy2 = fminf(bi[k].w, bj.w);
            float iw  = fmaxf(xx2 - xx1, 0.0f);
            float ih  = fmaxf(yy2 - yy1, 0.0f);
            float inter = iw * ih;
            unsigned p = (3.0f * inter > si[k] + aj) ? (1u << b) : 0u;
            if (k == 0) bits0 |= p;
            else if (k == 1) bits1 |= p;
            else if (k == 2) bits2 |= p;
            else bits3 |= p;
        }
    }
    size_t base = (size_t)rowbase * NWORDS + (size_t)cb * 32 + w;
    g_masks[base + (size_t)(r0 +  0) * NWORDS] = bits0;
    g_masks[base + (size_t)(r0 +  8) * NWORDS] = bits1;
    g_masks[base + (size_t)(r0 + 16) * NWORDS] = bits2;
    g_masks[base + (size_t)(r0 + 24) * NWORDS] = bits3;
}

// ---------------------------------------------------------------------------
// Kernel 4: cp.async-pipelined greedy scan, 128-box chunks (64 iterations).
//  Same schedule as R14 (verified): operands LDG'd 2 chunks ahead (4-slot
//  ring, 16B cp.async); keep-row gathers staged (4B cp.async) at iter c for
//  keeps(c-1), applied at iter c+2; wait_group 1 retires 2-iter-old groups.
//  sup_s lag = c-3 ; supfix = n1acc(c-1) | carry n2acc(c-2).
// ---------------------------------------------------------------------------
#define OPRING_BYTES (4 * 3 * 128 * 16)          // 24576
#define STAGE_BYTES  (4 * MAXK * NWORDS * 4)     // 32768
#define SCAN_SMEM    (OPRING_BYTES + STAGE_BYTES)

__global__ void __launch_bounds__(256)
scan_kernel(const float* __restrict__ scores, float* __restrict__ out) {
    extern __shared__ unsigned char dsm[];
    u64      (*opring)[3][128][2]   = (u64(*)[3][128][2])dsm;
    unsigned (*stage)[MAXK][NWORDS] = (unsigned(*)[MAXK][NWORDS])(dsm + OPRING_BYTES);

    __shared__ unsigned sup_s[NWORDS];
    __shared__ u64      ringkb[4][2];
    __shared__ u64      kbuf[2][2];
    __shared__ int      kcnt[2];
    __shared__ int      s_keep[NPAD];

    const int tid = threadIdx.x;
    sup_s[tid] = 0u;
    if (tid == 0) {
        kbuf[0][0] = kbuf[0][1] = kbuf[1][0] = kbuf[1][1] = 0ull;
        kcnt[0] = kcnt[1] = 0;
        #pragma unroll
        for (int s = 0; s < 4; s++) { ringkb[s][0] = 0ull; ringkb[s][1] = 0ull; }
    }

    const u64* m64 = (const u64*)g_masks;        // row stride = 128 u64
    const int e  = tid - 32;                     // bg task id 0..223
    const int w0 = e;                            // owned suppression word
    const int w1 = (e >= 0 && e < 32) ? e + 224 : -1;

    // ---- prologue: fill opring slots 0,1 (chunks 0,1) synchronously -------
    if (tid >= 32) {
        for (int t = e; t < 384; t += 224) {
            int row = t & 127, f = t >> 7;       // f: 0=conf 1=n1 2=n2
            int wi0 = 2 * (0 + f);               // chunk 0
            opring[0][f][row][0] = __ldg(m64 + (size_t)row * 128 + wi0);
            opring[0][f][row][1] = __ldg(m64 + (size_t)row * 128 + wi0 + 1);
            int wi1 = 2 * (1 + f);               // chunk 1
            opring[1][f][row][0] = __ldg(m64 + (size_t)(128 + row) * 128 + wi1);
            opring[1][f][row][1] = __ldg(m64 + (size_t)(128 + row) * 128 + wi1 + 1);
        }
    }
    __syncthreads();

    u64 supfix0 = 0, supfix1 = 0, carry0 = 0, carry1 = 0;   // thread 0 only
    int nk_local = 0;                                        // thread 0 only

    for (int c = 0; c < NCH2; c++) {
        // ---- pre-barrier: retire groups <= c-2, apply staged keeps(c-3) ----
        if (tid >= 32) {
            cp_wait1();
            if (c >= 3) {
                const int slot_a = (c - 2) & 3;
                u64 ka0 = ringkb[slot_a][0], ka1 = ringkb[slot_a][1];
                if (ka0 | ka1) {
                    unsigned acc0 = 0u, acc1 = 0u;
                    int s = 0;
                    const size_t pb = (size_t)(c - 3) * 128;
                    while (ka0) {
                        int l = __ffsll((long long)ka0) - 1; ka0 &= ka0 - 1;
                        if (s < MAXK) {
                            acc0 |= stage[slot_a][s][w0];
                            if (w1 >= 0) acc1 |= stage[slot_a][s][w1];
                        } else {
                            const unsigned* row = g_masks + (pb + l) * NWORDS;
                            acc0 |= __ldg(row + w0);
                            if (w1 >= 0) acc1 |= __ldg(row + w1);
                        }
                        s++;
                    }
                    while (ka1) {
                        int l = __ffsll((long long)ka1) - 1; ka1 &= ka1 - 1;
                        if (s < MAXK) {
                            acc0 |= stage[slot_a][s][w0];
                            if (w1 >= 0) acc1 |= stage[slot_a][s][w1];
                        } else {
                            const unsigned* row = g_masks + (pb + 64 + l) * NWORDS;
                            acc0 |= __ldg(row + w0);
                            if (w1 >= 0) acc1 |= __ldg(row + w1);
                        }
                        s++;
                    }
                    if (acc0) sup_s[w0] |= acc0;
                    if (w1 >= 0 && acc1) sup_s[w1] |= acc1;
                }
            }
        }
        __syncthreads();
        if (c > 0 && kcnt[(c - 1) & 1] >= NPAD) break;   // uniform

        if (tid == 0) {
            // ---- resolution: pure smem (2x u64 masks) ----
            const int slot = c & 3;
            const int base = c * 128;
            u64 sup0 = *(const u64*)&sup_s[4 * c];
            u64 sup1 = *(const u64*)&sup_s[4 * c + 2];
            u64 am0 = ~(sup0 | supfix0);
            u64 am1 = ~(sup1 | supfix1);
            u64 k0 = 0, k1 = 0, n1a0 = 0, n1a1 = 0, n2a0 = 0, n2a1 = 0;
            int k2 = nk_local;
            while (am0 | am1) {
                int idx;
                if (am0) idx = __ffsll((long long)am0) - 1;
                else     idx = 64 + __ffsll((long long)am1) - 1;
                if (idx < 64) k0 |= 1ull << idx;
                else          k1 |= 1ull << (idx - 64);
                n1a0 |= opring[slot][1][idx][0];  n1a1 |= opring[slot][1][idx][1];
                n2a0 |= opring[slot][2][idx][0];  n2a1 |= opring[slot][2][idx][1];
                am0 &= ~opring[slot][0][idx][0];
                am1 &= ~opring[slot][0][idx][1];
                if (idx < 64) am0 &= ~(1ull << idx);
                else          am1 &= ~(1ull << (idx - 64));
                if (k2 < NPAD) s_keep[k2++] = base + idx;
            }
            kbuf[c & 1][0] = k0;  kbuf[c & 1][1] = k1;
            kcnt[c & 1] = k2;     nk_local = k2;
            supfix0 = carry0 | n1a0;  supfix1 = carry1 | n1a1;
            carry0  = n2a0;           carry1  = n2a1;
        } else if (tid >= 32) {
            // ---- issue keep-row gathers for keeps(c-1) into stage[c&3] ----
            if (c >= 1) {
                u64 km0 = kbuf[(c - 1) & 1][0];
                u64 km1 = kbuf[(c - 1) & 1][1];
                if (tid == 32) { ringkb[c & 3][0] = km0; ringkb[c & 3][1] = km1; }
                int s = 0;
                const size_t pb = (size_t)(c - 1) * 128;
                while (km0 && s < MAXK) {
                    int l = __ffsll((long long)km0) - 1; km0 &= km0 - 1;
                    const unsigned* row = g_masks + (pb + l) * NWORDS;
                    cp_async4(&stage[c & 3][s][w0], row + w0);
                    if (w1 >= 0) cp_async4(&stage[c & 3][s][w1], row + w1);
                    s++;
                }
                while (km1 && s < MAXK) {
                    int l = __ffsll((long long)km1) - 1; km1 &= km1 - 1;
                    const unsigned* row = g_masks + (pb + 64 + l) * NWORDS;
                    cp_async4(&stage[c & 3][s][w0], row + w0);
                    if (w1 >= 0) cp_async4(&stage[c & 3][s][w1], row + w1);
                    s++;
                }
            }
            // ---- issue operand prefetch for chunk c+2 (16B cp.async) ----
            const int cf = c + 2;
            if (cf < NCH2) {
                for (int t = e; t < 384; t += 224) {
                    int row = t & 127, f = t >> 7;
                    int wi = 2 * (cf + f);
                    if (wi > 126) wi = 126;          // tail clamp; unused data
                    cp_async16(&opring[cf & 3][f][row][0],
                               m64 + (size_t)(128 * cf + row) * 128 + wi);
                }
            }
            cp_commit();    // exactly one group per bg thread per iteration
        }
    }
    __syncthreads();
    const int nk = (kcnt[0] > kcnt[1]) ? kcnt[0] : kcnt[1];

    // ---- outputs: boxes (300*4) then scores (300*81); zero invalid rows ----
    for (int idx = tid; idx < NPAD * 4; idx += 256) {
        int r = idx >> 2, cc = idx & 3;
        float v = 0.0f;
        if (r < nk) {
            float4 b = g_sbox[s_keep[r]];
            v = (cc == 0) ? b.x : (cc == 1) ? b.y : (cc == 2) ? b.z : b.w;
        }
        out[idx] = v;
    }
    for (int idx = tid; idx < NPAD * CLS; idx += 256) {
        int r = idx / CLS, cc = idx - r * CLS;
        float v = 0.0f;
        if (r < nk)
            v = scores[(size_t)g_orig[s_keep[r]] * CLS + cc];
        out[NPAD * 4 + idx] = v;
    }
}

// ---------------------------------------------------------------------------
extern "C" void kernel_launch(void* const* d_in, const int* in_sizes, int n_in,
                              void* d_out, int out_size) {
    const float* meta      = (const float*)d_in[0];
    const float* deltas    = (const float*)d_in[1];
    const float* proposals = (const float*)d_in[2];
    const float* scores    = (const float*)d_in[3];
    float* out = (float*)d_out;

    decode_kernel<<<NBOX / 8, 256>>>(meta, deltas, proposals, scores);

    cudaFuncSetAttribute(rank_kernel,
                         cudaFuncAttributeMaxDynamicSharedMemorySize, 65536);
    rank_kernel<<<256, 256, 65536>>>();

    mask_kernel<<<1152, 256>>>();

    cudaFuncSetAttribute(scan_kernel,
                         cudaFuncAttributeMaxDynamicSharedMemorySize, SCAN_SMEM);
    scan_kernel<<<1, 256, SCAN_SMEM>>>(scores, out);
}